// round 15
// baseline (speedup 1.0000x reference)
#include <cuda_runtime.h>
#include <cuda_fp16.h>
#include <math.h>
#include <stdint.h>

#define B_ 8192
#define D_ 256
#define H_ 266
#define HP 272
#define T_ 20
#define NBLK 128
#define THREADS 512
#define EPS 1e-5f

typedef __half hf;

// ---------------- persistent state (no allocation allowed) ----------------
__device__ float g_x[B_ * D_];
__device__ hf g_xh[B_ * D_];
__device__ hf g_h1[B_ * HP];
__device__ hf g_h2[B_ * HP];
__device__ float g_as[3 * 288];   // rotating atomic column-sum slots
__device__ float g_aq[3 * 288];
__device__ float g_ps0[NBLK];
__device__ float g_pq0[NBLK];
__device__ unsigned g_cnt8[16];   // hierarchical barrier: 16 groups of 8 CTAs
__device__ unsigned g_cnt;
__device__ unsigned g_epoch;

// fp16 weights, K-padded so every row is 16B aligned
#define GW1 0                 // T*266 rows, stride 256
#define GW2 1361920           // T*266 rows, stride 272
#define GW3 2808960           // T*256 rows, stride 272
#define GVW1 4201600          // 266 rows, stride 256
#define GVW2 4269696          // 266 rows, stride 272
#define GWTOT 4342048
__device__ hf g_w[GWTOT];

// ---------------- smem layout (byte offsets) ----------------
// 4 stages of (A 64x72 hf = 9216B) + (B 288x72 hf = 41472B) = 50688B each
#define STGB 50688
#define OFF_SC 202752   // float[288]
#define OFF_SH 203904   // float[288]
#define OFF_SC2 205056  // half2[144]
#define OFF_SH2 205632  // half2[144]
#define OFF_RED 206208  // float[1280]
#define OFF_VS 211328   // float[64]
#define OFF_BC 211584   // float[8]
#define SMEM_BYTES 211616

// ---------------- low-level helpers ----------------
__device__ __forceinline__ uint32_t smem_u32(const void* p) {
    uint32_t a;
    asm("{ .reg .u64 t; cvta.to.shared.u64 t, %1; cvt.u32.u64 %0, t; }" : "=r"(a) : "l"(p));
    return a;
}
__device__ __forceinline__ void cpa16(uint32_t dst, const void* src, int sz) {
    asm volatile("cp.async.cg.shared.global [%0], [%1], 16, %2;" :: "r"(dst), "l"(src),
                 "r"(sz));
}
__device__ __forceinline__ uint32_t packhf(float a, float b) {
    __half2 t = __floats2half2_rn(a, b);
    return *(uint32_t*)&t;
}
#define MMAH(d, a, b0, b1)                                                    \
    asm volatile(                                                             \
        "mma.sync.aligned.m16n8k16.row.col.f32.f16.f16.f32 "                  \
        "{%0,%1,%2,%3},{%4,%5,%6,%7},{%8,%9},{%0,%1,%2,%3};"                  \
        : "+f"(d[0]), "+f"(d[1]), "+f"(d[2]), "+f"(d[3])                      \
        : "r"(a[0]), "r"(a[1]), "r"(a[2]), "r"(a[3]), "r"(b0), "r"(b1))
#define LDSM4(r, ad)                                                          \
    asm volatile("ldmatrix.sync.aligned.m8n8.x4.shared.b16 {%0,%1,%2,%3}, [%4];" \
                 : "=r"((r)[0]), "=r"((r)[1]), "=r"((r)[2]), "=r"((r)[3])     \
                 : "r"(ad))
#define LDSM2(r0, r1, ad)                                                     \
    asm volatile("ldmatrix.sync.aligned.m8n8.x2.shared.b16 {%0,%1}, [%2];"    \
                 : "=r"(r0), "=r"(r1) : "r"(ad))

// hierarchical epoch-based global barrier: 8-way group arrival, 16-way root
__device__ __forceinline__ void gbar(int bid) {
    __syncthreads();
    if (threadIdx.x == 0) {
        unsigned e0 = *(volatile unsigned*)&g_epoch;
        __threadfence();
        unsigned o = atomicAdd(&g_cnt8[bid >> 3], 1u);
        if (o == 7u) {
            unsigned r = atomicAdd(&g_cnt, 1u);
            if (r == 15u) {
                *(volatile unsigned*)&g_cnt = 0u;
#pragma unroll
                for (int g = 0; g < 16; g++) *(volatile unsigned*)&g_cnt8[g] = 0u;
                __threadfence();
                atomicAdd(&g_epoch, 1u);
            } else {
                while (*(volatile unsigned*)&g_epoch == e0) { __nanosleep(32); }
            }
        } else {
            while (*(volatile unsigned*)&g_epoch == e0) { __nanosleep(32); }
        }
        __threadfence();
    }
    __syncthreads();
}

// ---------------- finalize from atomic totals: read 2.1KB, compute sc/sh, zero stale ----
__device__ __forceinline__ void finalize_direct(int slot, int zslot,
                                                const float* __restrict__ bng,
                                                const float* __restrict__ bnb,
                                                char* smc, int tid) {
    float* scS = (float*)(smc + OFF_SC);
    float* shS = (float*)(smc + OFF_SH);
    __half2* sc2 = (__half2*)(smc + OFF_SC2);
    __half2* sh2 = (__half2*)(smc + OFF_SH2);
    if (tid < 288) {
        if (tid < H_) {
            float s = g_as[slot * 288 + tid];
            float q = g_aq[slot * 288 + tid];
            float mean = s * (1.f / B_);
            float var = q * (1.f / B_) - mean * mean;
            float inv = rsqrtf(var + EPS);
            float sc = bng[tid] * inv;
            scS[tid] = sc;
            shS[tid] = bnb[tid] - mean * sc;
        } else {
            scS[tid] = 0.f;
            shS[tid] = 0.f;
        }
        g_as[zslot * 288 + tid] = 0.f;
        g_aq[zslot * 288 + tid] = 0.f;
    }
    __syncthreads();
    if (tid < 144) {
        sc2[tid] = __floats2half2_rn(scS[2 * tid], scS[2 * tid + 1]);
        sh2[tid] = __floats2half2_rn(shS[2 * tid], shS[2 * tid + 1]);
    }
    __syncthreads();
}

// ---------------- cp.async chunk issue (64-k chunks, row stride 72 hf) ----------------
// Skips pad B rows (>=266: zeroed once at start) and out-of-K segments (never read).
__device__ __forceinline__ void issue_chunk(const hf* __restrict__ Ag,
                                            const hf* __restrict__ Wg, int klim,
                                            int nact, char* smc, int bid, int tid,
                                            int ch) {
    hf* As = (hf*)(smc + (ch & 3) * STGB);
    hf* Bs = As + 4608;
    const int gm0 = bid * 64;
#pragma unroll
    for (int l = 0; l < 6; l++) {
        int i = tid + l * THREADS;
        if (i < 512) {
            int row = i >> 3, seg = i & 7, gk = ch * 64 + seg * 8;
            if (gk + 8 <= klim)
                cpa16(smem_u32(As + row * 72 + seg * 8),
                      Ag + (size_t)(gm0 + row) * klim + gk, 16);
        } else if (i < 2640) {
            int j = i - 512;
            int n = j >> 3, seg = j & 7, gk = ch * 64 + seg * 8;
            if (n < 266 && gk + 8 <= klim) {
                int sz = (n < nact) ? 16 : 0;  // zero-fill rows [nact,266)
                const hf* src = Wg + (sz ? ((size_t)n * klim + gk) : 0);
                cpa16(smem_u32(Bs + n * 72 + seg * 8), src, sz);
            }
        }
    }
    asm volatile("cp.async.commit_group;" ::: "memory");
}

__device__ __forceinline__ void issue3(const hf* Ag, const hf* Wg, int klim, int nact,
                                       char* smc, int bid, int tid) {
    issue_chunk(Ag, Wg, klim, nact, smc, bid, tid, 0);
    issue_chunk(Ag, Wg, klim, nact, smc, bid, tid, 1);
    issue_chunk(Ag, Wg, klim, nact, smc, bid, tid, 2);
}

// ---------------- GEMM mainloop (chunks 0,1,2 pre-issued by caller; 4 stages) -----------
// NC chunks of k=64; the last chunk runs LASTSL k16-slabs (others run 4).
template <int NC, int LASTSL, bool AFFINE>
__device__ __forceinline__ void do_gemm(const hf* __restrict__ Ag,
                                        const hf* __restrict__ Wg, int klim, int nact,
                                        int ntot, int slot, int zslot,
                                        const float* __restrict__ bng,
                                        const float* __restrict__ bnb, char* smc,
                                        int bid, int tid, float acc[2][5][4]) {
    const int lane = tid & 31, w = tid >> 5, wm = w >> 3, wn = w & 7;
    int ntw, cbase;
    if (ntot == 256) {
        ntw = 4;
        cbase = wn * 32;
    } else {
        ntw = (wn < 4) ? 5 : 4;
        cbase = (wn < 4) ? wn * 40 : 160 + (wn - 4) * 32;
    }
    const __half2* sc2 = (const __half2*)(smc + OFF_SC2);
    const __half2* sh2 = (const __half2*)(smc + OFF_SH2);

    if (AFFINE) finalize_direct(slot, zslot, bng, bnb, smc, tid);

    const int jj = lane >> 3, rw = lane & 7;
    const int am_off = (jj & 1) * 8 + rw;
    const int ak_off = (jj >> 1) * 8;

    for (int ch = 0; ch < NC; ch++) {
        const int rem = NC - 1 - ch;
        if (rem >= 2)
            asm volatile("cp.async.wait_group 2;" ::: "memory");
        else if (rem == 1)
            asm volatile("cp.async.wait_group 1;" ::: "memory");
        else
            asm volatile("cp.async.wait_group 0;" ::: "memory");
        __syncthreads();
        if (ch + 3 < NC) issue_chunk(Ag, Wg, klim, nact, smc, bid, tid, ch + 3);

        const hf* As = (const hf*)(smc + (ch & 3) * STGB);
        const hf* Bs = As + 4608;
        const int smax = (ch == NC - 1) ? LASTSL : 4;
#pragma unroll
        for (int sl = 0; sl < 4; sl++) {
            if (sl >= smax) break;
            uint32_t a[2][4];
#pragma unroll
            for (int mt = 0; mt < 2; mt++) {
                const int r = wm * 32 + mt * 16 + am_off;
                LDSM4(a[mt], smem_u32(As + r * 72 + sl * 16 + ak_off));
            }
            if (AFFINE) {
                const int idx = ch * 32 + sl * 8 + (lane & 3);
                const __half2 s0 = sc2[idx], h0 = sh2[idx];
                const __half2 s4 = sc2[idx + 4], h4 = sh2[idx + 4];
                const __half2 z = __floats2half2_rn(0.f, 0.f);
#pragma unroll
                for (int mt = 0; mt < 2; mt++) {
                    __half2 v;
                    v = *(__half2*)&a[mt][0];
                    v = __hmax2(__hfma2(v, s0, h0), z);
                    a[mt][0] = *(uint32_t*)&v;
                    v = *(__half2*)&a[mt][1];
                    v = __hmax2(__hfma2(v, s0, h0), z);
                    a[mt][1] = *(uint32_t*)&v;
                    v = *(__half2*)&a[mt][2];
                    v = __hmax2(__hfma2(v, s4, h4), z);
                    a[mt][2] = *(uint32_t*)&v;
                    v = *(__half2*)&a[mt][3];
                    v = __hmax2(__hfma2(v, s4, h4), z);
                    a[mt][3] = *(uint32_t*)&v;
                }
            }
            uint32_t b[5][2];
#pragma unroll
            for (int p = 0; p < 2; p++) {
                const int ntp = p * 2 + (jj >> 1);
                const int kb = (jj & 1) * 8;
                const int rowb = cbase + ntp * 8 + rw;
                uint32_t r4[4];
                LDSM4(r4, smem_u32(Bs + rowb * 72 + sl * 16 + kb));
                b[2 * p][0] = r4[0];
                b[2 * p][1] = r4[1];
                b[2 * p + 1][0] = r4[2];
                b[2 * p + 1][1] = r4[3];
            }
            if (ntw == 5) {
                const int kb = (jj & 1) * 8;
                const int rowb = cbase + 32 + rw;
                LDSM2(b[4][0], b[4][1], smem_u32(Bs + rowb * 72 + sl * 16 + kb));
            }
#pragma unroll
            for (int nt = 0; nt < 5; nt++) {
                if (nt < ntw) {
                    MMAH(acc[0][nt], a[0], b[nt][0], b[nt][1]);
                    MMAH(acc[1][nt], a[1], b[nt][0], b[nt][1]);
                }
            }
        }
    }
    __syncthreads();
}

// ---------------- epilogue: bias, hf Y store, column stats -> atomic slot ----------------
__device__ __forceinline__ void epi_stats(float acc[2][5][4], const float* __restrict__ bias,
                                          hf* __restrict__ Yg, int N_ACT, int slot,
                                          char* smc, int bid, int tid) {
    const int lane = tid & 31, w = tid >> 5, wm = w >> 3, wn = w & 7;
    const int ntw = (wn < 4) ? 5 : 4;
    const int cbase = (wn < 4) ? wn * 40 : 160 + (wn - 4) * 32;
    float* ps = (float*)(smc + OFF_RED);
    float* pq = ps + 640;
#pragma unroll
    for (int nt = 0; nt < 5; nt++) {
        if (nt >= ntw) continue;
        const int c0 = cbase + nt * 8 + 2 * (lane & 3);
        float b0 = 0.f, b1 = 0.f;
        if (c0 < N_ACT) { b0 = bias[c0]; b1 = bias[c0 + 1]; }
        float s0 = 0.f, s1 = 0.f, q0 = 0.f, q1 = 0.f;
#pragma unroll
        for (int mt = 0; mt < 2; mt++) {
            const int rbase = bid * 64 + wm * 32 + mt * 16 + (lane >> 2);
#pragma unroll
            for (int rs = 0; rs < 2; rs++) {
                float y0 = acc[mt][nt][rs * 2 + 0] + b0;
                float y1 = acc[mt][nt][rs * 2 + 1] + b1;
                const int row = rbase + rs * 8;
                if (c0 < N_ACT)
                    *(uint32_t*)(Yg + (size_t)row * HP + c0) = packhf(y0, y1);
                else if (c0 < HP)
                    *(uint32_t*)(Yg + (size_t)row * HP + c0) = 0u;
                s0 += y0; s1 += y1;
                q0 += y0 * y0; q1 += y1 * y1;
            }
        }
#pragma unroll
        for (int m = 4; m <= 16; m <<= 1) {
            s0 += __shfl_xor_sync(~0u, s0, m);
            s1 += __shfl_xor_sync(~0u, s1, m);
            q0 += __shfl_xor_sync(~0u, q0, m);
            q1 += __shfl_xor_sync(~0u, q1, m);
        }
        if (lane < 4) {
            ps[w * 40 + nt * 8 + 2 * lane] = s0;
            ps[w * 40 + nt * 8 + 2 * lane + 1] = s1;
            pq[w * 40 + nt * 8 + 2 * lane] = q0;
            pq[w * 40 + nt * 8 + 2 * lane + 1] = q1;
        }
    }
    __syncthreads();
    if (tid < H_) {
        const int n = tid;
        const int wn2 = (n < 160) ? (n / 40) : (4 + (n - 160) / 32);
        const int loc = (n < 160) ? (n % 40) : ((n - 160) % 32);
        float s = ps[wn2 * 40 + loc] + ps[(8 + wn2) * 40 + loc];
        float q = pq[wn2 * 40 + loc] + pq[(8 + wn2) * 40 + loc];
        atomicAdd(&g_as[slot * 288 + n], s);
        atomicAdd(&g_aq[slot * 288 + n], q);
    }
    __syncthreads();
}

// ---------------- L3 epilogue fused with SDE update (N=256) ----------------
__device__ __forceinline__ void epi_update(float acc[2][5][4], const float* __restrict__ b3,
                                           const float* __restrict__ xi_t,
                                           const float* __restrict__ xsrc,
                                           float* __restrict__ xdst,
                                           hf* __restrict__ xh, float ht, char* smc,
                                           int bid, int tid) {
    const int lane = tid & 31, w = tid >> 5, wm = w >> 3, wn = w & 7;
    const int cbase = wn * 32;
    const float sq = sqrtf(ht);
    float fa[2][2] = {}, da[2][2] = {};
#pragma unroll
    for (int nt = 0; nt < 4; nt++) {
        const int c0 = cbase + nt * 8 + 2 * (lane & 3);
        const float b0 = b3[c0], b1 = b3[c0 + 1];
#pragma unroll
        for (int mt = 0; mt < 2; mt++) {
#pragma unroll
            for (int rs = 0; rs < 2; rs++) {
                const int row = bid * 64 + wm * 32 + mt * 16 + (lane >> 2) + rs * 8;
                float gg0 = acc[mt][nt][rs * 2 + 0] + b0;
                float gg1 = acc[mt][nt][rs * 2 + 1] + b1;
                float2 xi2 = *(const float2*)(xi_t + (size_t)row * 256 + c0);
                float2 xs2 = *(const float2*)(xsrc + (size_t)row * 256 + c0);
                float n0 = sq * xi2.x, n1 = sq * xi2.y;
                fa[mt][rs] += gg0 * gg0 + gg1 * gg1;
                da[mt][rs] += gg0 * n0 + gg1 * n1;
                float xn0 = xs2.x - gg0 * ht + n0;
                float xn1 = xs2.y - gg1 * ht + n1;
                *(float2*)(xdst + (size_t)row * 256 + c0) = make_float2(xn0, xn1);
                if (xh)
                    *(uint32_t*)(xh + (size_t)row * 256 + c0) = packhf(xn0, xn1);
            }
        }
    }
#pragma unroll
    for (int m = 1; m <= 2; m <<= 1) {
#pragma unroll
        for (int mt = 0; mt < 2; mt++)
#pragma unroll
            for (int rs = 0; rs < 2; rs++) {
                fa[mt][rs] += __shfl_xor_sync(~0u, fa[mt][rs], m);
                da[mt][rs] += __shfl_xor_sync(~0u, da[mt][rs], m);
            }
    }
    float* rf = (float*)(smc + OFF_RED);
    float* rd = rf + 512;
    if ((lane & 3) == 0) {
#pragma unroll
        for (int mt = 0; mt < 2; mt++)
#pragma unroll
            for (int rs = 0; rs < 2; rs++) {
                int rl = wm * 32 + mt * 16 + (lane >> 2) + rs * 8;
                rf[wn * 64 + rl] = fa[mt][rs];
                rd[wn * 64 + rl] = da[mt][rs];
            }
    }
    __syncthreads();
    float* vs = (float*)(smc + OFF_VS);
    if (tid < 64) {
        float F = 0.f, Dt = 0.f;
#pragma unroll
        for (int j = 0; j < 8; j++) {
            F += rf[j * 64 + tid];
            Dt += rd[j * 64 + tid];
        }
        vs[tid] += -F * ht + Dt;
    }
    __syncthreads();
}

// ---------------- v0 tail ----------------
__device__ __forceinline__ void v3_part(const hf* __restrict__ h2,
                                        const float* __restrict__ vW3,
                                        const float* __restrict__ vb3, char* smc,
                                        int bid, int tid) {
    const int lane = tid & 31, w = tid >> 5;
    const float* scS = (const float*)(smc + OFF_SC);
    const float* shS = (const float*)(smc + OFF_SH);
    float* yv = (float*)(smc + OFF_RED);
    for (int i = 0; i < 4; i++) {
        int row = w * 4 + i;
        size_t base = (size_t)(bid * 64 + row) * HP;
        float s = 0.f;
        for (int k = lane; k < H_; k += 32) {
            float hv = __half2float(h2[base + k]);
            float a2 = fmaxf(fmaf(hv, scS[k], shS[k]), 0.f);
            s = fmaf(a2, vW3[k], s);
        }
#pragma unroll
        for (int m = 16; m > 0; m >>= 1) s += __shfl_xor_sync(~0u, s, m);
        if (lane == 0) yv[row] = s + vb3[0];
    }
    __syncthreads();
    if (tid == 0) {
        float s = 0.f, q = 0.f;
        for (int i = 0; i < 64; i++) {
            float t = yv[i];
            s += t;
            q = fmaf(t, t, q);
        }
        g_ps0[bid] = s;
        g_pq0[bid] = q;
    }
    __syncthreads();
}

__device__ __forceinline__ void v0_final(const float* __restrict__ vg3,
                                         const float* __restrict__ vbe3, char* smc,
                                         int tid) {
    float* yv = (float*)(smc + OFF_RED);
    float* bc = (float*)(smc + OFF_BC);
    float* vs = (float*)(smc + OFF_VS);
    if (tid == 0) {
        float s = 0.f, q = 0.f;
        for (int b = 0; b < NBLK; b++) { s += g_ps0[b]; q += g_pq0[b]; }
        float m = s * (1.f / B_);
        float var = q * (1.f / B_) - m * m;
        float inv = rsqrtf(var + EPS);
        float sc = vg3[0] * inv;
        bc[0] = sc;
        bc[1] = vbe3[0] - m * sc;
    }
    __syncthreads();
    if (tid < 64) vs[tid] = fmaxf(fmaf(yv[tid], bc[0], bc[1]), 0.f);
    __syncthreads();
}

// ---------------- the persistent mega-kernel ----------------
__global__ void __launch_bounds__(THREADS, 1) mega(
    const float* __restrict__ x, const float* __restrict__ xi,
    const float* __restrict__ tg, const float* __restrict__ W1,
    const float* __restrict__ b1, const float* __restrict__ g1,
    const float* __restrict__ be1, const float* __restrict__ W2,
    const float* __restrict__ b2, const float* __restrict__ g2,
    const float* __restrict__ be2, const float* __restrict__ W3,
    const float* __restrict__ b3, const float* __restrict__ vW1,
    const float* __restrict__ vb1, const float* __restrict__ vg1,
    const float* __restrict__ vbe1, const float* __restrict__ vW2,
    const float* __restrict__ vb2, const float* __restrict__ vg2,
    const float* __restrict__ vbe2, const float* __restrict__ vW3,
    const float* __restrict__ vb3, const float* __restrict__ vg3,
    const float* __restrict__ vbe3, float* __restrict__ out) {
    extern __shared__ char smc[];
    const int bid = blockIdx.x, tid = threadIdx.x;

    // ---- phase 0: convert weights + x to fp16; zero atomic slots + pad B rows ----
    {
        const int gt = bid * THREADS + tid, gs = NBLK * THREADS;
        for (int i = gt; i < T_ * H_ * D_; i += gs)
            g_w[GW1 + i] = __float2half(W1[i]);
        for (int i = gt; i < T_ * H_ * HP; i += gs) {
            int r = i / HP, k = i - r * HP;
            g_w[GW2 + i] = (k < H_) ? __float2half(W2[r * H_ + k]) : __float2half(0.f);
        }
        for (int i = gt; i < T_ * D_ * HP; i += gs) {
            int r = i / HP, k = i - r * HP;
            g_w[GW3 + i] = (k < H_) ? __float2half(W3[r * H_ + k]) : __float2half(0.f);
        }
        for (int i = gt; i < H_ * D_; i += gs)
            g_w[GVW1 + i] = __float2half(vW1[i]);
        for (int i = gt; i < H_ * HP; i += gs) {
            int r = i / HP, k = i - r * HP;
            g_w[GVW2 + i] = (k < H_) ? __float2half(vW2[r * H_ + k]) : __float2half(0.f);
        }
        for (int i = gt; i < B_ * D_; i += gs) g_xh[i] = __float2half(x[i]);
        for (int i = gt; i < 3 * 288; i += gs) {
            g_as[i] = 0.f;
            g_aq[i] = 0.f;
        }
        // zero the always-pad B rows [266,288) in all 4 stages (never re-written)
        for (int i = tid; i < 4 * 22 * 36; i += THREADS) {
            int st = i / (22 * 36), rr = (i / 36) % 22, c = i % 36;
            *(uint32_t*)(smc + st * STGB + 9216 + (266 + rr) * 144 + c * 4) = 0u;
        }
    }
    gbar(bid);

    int bn = 0;  // vector-BN counter (slot = bn % 3)

    // ---- v0 network ----
    issue3(g_xh, g_w + GVW1, 256, 266, smc, bid, tid);
    {
        float acc[2][5][4] = {};
        do_gemm<4, 4, false>(g_xh, g_w + GVW1, 256, 266, 288, 0, 0, nullptr, nullptr,
                             smc, bid, tid, acc);
        epi_stats(acc, vb1, g_h1, 266, bn % 3, smc, bid, tid);
    }
    issue3(g_h1, g_w + GVW2, 272, 266, smc, bid, tid);
    gbar(bid);
    {
        float acc[2][5][4] = {};
        do_gemm<5, 1, true>(g_h1, g_w + GVW2, 272, 266, 288, bn % 3, (bn + 2) % 3, vg1,
                            vbe1, smc, bid, tid, acc);
        bn++;
        epi_stats(acc, vb2, g_h2, 266, bn % 3, smc, bid, tid);
    }
    gbar(bid);
    finalize_direct(bn % 3, (bn + 2) % 3, vg2, vbe2, smc, tid);
    bn++;
    v3_part(g_h2, vW3, vb3, smc, bid, tid);
    gbar(bid);
    v0_final(vg3, vbe3, smc, tid);

    issue3(g_xh, g_w + GW1, 256, 266, smc, bid, tid);

    // ---- time-stepping scan ----
    for (int t = 0; t < T_; t++) {
        const float* xsrc = (t == 0) ? x : g_x;
        const hf* W1t = g_w + GW1 + (size_t)t * H_ * D_;
        const hf* W2t = g_w + GW2 + (size_t)t * H_ * HP;
        const hf* W3t = g_w + GW3 + (size_t)t * D_ * HP;
        const float* b1t = b1 + (size_t)t * H_;
        const float* g1t = g1 + (size_t)t * H_;
        const float* be1t = be1 + (size_t)t * H_;
        const float* b2t = b2 + (size_t)t * H_;
        const float* g2t = g2 + (size_t)t * H_;
        const float* be2t = be2 + (size_t)t * H_;
        const float* b3t = b3 + (size_t)t * D_;
        const float* xit = xi + (size_t)t * B_ * D_;

        {
            float acc[2][5][4] = {};
            do_gemm<4, 4, false>(g_xh, W1t, 256, 266, 288, 0, 0, nullptr, nullptr, smc,
                                 bid, tid, acc);
            epi_stats(acc, b1t, g_h1, 266, bn % 3, smc, bid, tid);
        }
        issue3(g_h1, W2t, 272, 266, smc, bid, tid);
        gbar(bid);
        {
            float acc[2][5][4] = {};
            do_gemm<5, 1, true>(g_h1, W2t, 272, 266, 288, bn % 3, (bn + 2) % 3, g1t,
                                be1t, smc, bid, tid, acc);
            bn++;
            epi_stats(acc, b2t, g_h2, 266, bn % 3, smc, bid, tid);
        }
        issue3(g_h2, W3t, 272, 256, smc, bid, tid);
        gbar(bid);
        {
            float acc[2][5][4] = {};
            do_gemm<5, 1, true>(g_h2, W3t, 272, 256, 256, bn % 3, (bn + 2) % 3, g2t,
                                be2t, smc, bid, tid, acc);
            bn++;
            float ht = tg[t + 1] - tg[t];
            float* xdst = (t == T_ - 1) ? (out + B_) : g_x;
            hf* xh = (t == T_ - 1) ? nullptr : g_xh;
            epi_update(acc, b3t, xit, xsrc, xdst, xh, ht, smc, bid, tid);
        }
        if (t + 1 < T_) {
            issue3(g_xh, g_w + GW1 + (size_t)(t + 1) * H_ * D_, 256, 266, smc, bid, tid);
        }
    }

    // ---- output v ----
    if (tid < 64) out[bid * 64 + tid] = ((float*)(smc + OFF_VS))[tid];
}

// ---------------- host ----------------
extern "C" void kernel_launch(void* const* d_in, const int* in_sizes, int n_in,
                              void* d_out, int out_size) {
    const float* x    = (const float*)d_in[0];
    const float* xi   = (const float*)d_in[1];
    const float* tg   = (const float*)d_in[2];
    const float* W1   = (const float*)d_in[3];
    const float* b1   = (const float*)d_in[4];
    const float* g1   = (const float*)d_in[5];
    const float* be1  = (const float*)d_in[6];
    const float* W2   = (const float*)d_in[7];
    const float* b2   = (const float*)d_in[8];
    const float* g2   = (const float*)d_in[9];
    const float* be2  = (const float*)d_in[10];
    const float* W3   = (const float*)d_in[11];
    const float* b3   = (const float*)d_in[12];
    const float* vW1  = (const float*)d_in[13];
    const float* vb1  = (const float*)d_in[14];
    const float* vg1  = (const float*)d_in[15];
    const float* vbe1 = (const float*)d_in[16];
    const float* vW2  = (const float*)d_in[17];
    const float* vb2  = (const float*)d_in[18];
    const float* vg2  = (const float*)d_in[19];
    const float* vbe2 = (const float*)d_in[20];
    const float* vW3  = (const float*)d_in[21];
    const float* vb3  = (const float*)d_in[22];
    const float* vg3  = (const float*)d_in[23];
    const float* vbe3 = (const float*)d_in[24];

    cudaFuncSetAttribute(mega, cudaFuncAttributeMaxDynamicSharedMemorySize, SMEM_BYTES);
    mega<<<NBLK, THREADS, SMEM_BYTES>>>(x, xi, tg, W1, b1, g1, be1, W2, b2, g2, be2,
                                        W3, b3, vW1, vb1, vg1, vbe1, vW2, vb2, vg2,
                                        vbe2, vW3, vb3, vg3, vbe3, (float*)d_out);
}

// round 16
// speedup vs baseline: 1.0289x; 1.0289x over previous
#include <cuda_runtime.h>
#include <cuda_fp16.h>
#include <math.h>
#include <stdint.h>

#define B_ 8192
#define D_ 256
#define H_ 266
#define HP 272
#define T_ 20
#define NBLK 128
#define THREADS 512
#define EPS 1e-5f

typedef __half hf;

// ---------------- persistent state (no allocation allowed) ----------------
__device__ float g_x[B_ * D_];
__device__ hf g_xh[B_ * D_];
__device__ hf g_h1[B_ * HP];
__device__ hf g_h2[B_ * HP];
__device__ float g_as[3 * 288];   // rotating atomic column-sum slots
__device__ float g_aq[3 * 288];
__device__ float g_ps0[NBLK];
__device__ float g_pq0[NBLK];
__device__ unsigned g_cnt;
__device__ unsigned g_epoch;

// fp16 weights, K-padded so every row is 16B aligned
#define GW1 0                 // T*266 rows, stride 256
#define GW2 1361920           // T*266 rows, stride 272
#define GW3 2808960           // T*256 rows, stride 272
#define GVW1 4201600          // 266 rows, stride 256
#define GVW2 4269696          // 266 rows, stride 272
#define GWTOT 4342048
__device__ hf g_w[GWTOT];

// ---------------- smem layout (byte offsets) ----------------
// stage: A 64x72 hf (9216B) + B 288x72 hf (41472B) = 50688B; 3 stages
#define STGB 50688
#define OFF_SC 152064   // float[288]
#define OFF_SH 153216   // float[288]
#define OFF_SC2 154368  // half2[144]
#define OFF_SH2 154944  // half2[144]
#define OFF_RED 155520  // float[1280]
#define OFF_VS 160640   // float[64]
#define OFF_BC 160896   // float[8]
#define OFF_EP 160928   // unsigned[1]: stashed barrier epoch
#define SMEM_BYTES 160932

// ---------------- low-level helpers ----------------
__device__ __forceinline__ uint32_t smem_u32(const void* p) {
    uint32_t a;
    asm("{ .reg .u64 t; cvta.to.shared.u64 t, %1; cvt.u32.u64 %0, t; }" : "=r"(a) : "l"(p));
    return a;
}
__device__ __forceinline__ void cpa16(uint32_t dst, const void* src, int sz) {
    asm volatile("cp.async.cg.shared.global [%0], [%1], 16, %2;" :: "r"(dst), "l"(src),
                 "r"(sz));
}
__device__ __forceinline__ uint32_t packhf(float a, float b) {
    __half2 t = __floats2half2_rn(a, b);
    return *(uint32_t*)&t;
}
#define MMAH(d, a, b0, b1)                                                    \
    asm volatile(                                                             \
        "mma.sync.aligned.m16n8k16.row.col.f32.f16.f16.f32 "                  \
        "{%0,%1,%2,%3},{%4,%5,%6,%7},{%8,%9},{%0,%1,%2,%3};"                  \
        : "+f"(d[0]), "+f"(d[1]), "+f"(d[2]), "+f"(d[3])                      \
        : "r"(a[0]), "r"(a[1]), "r"(a[2]), "r"(a[3]), "r"(b0), "r"(b1))
#define LDSM4(r, ad)                                                          \
    asm volatile("ldmatrix.sync.aligned.m8n8.x4.shared.b16 {%0,%1,%2,%3}, [%4];" \
                 : "=r"((r)[0]), "=r"((r)[1]), "=r"((r)[2]), "=r"((r)[3])     \
                 : "r"(ad))
#define LDSM2(r0, r1, ad)                                                     \
    asm volatile("ldmatrix.sync.aligned.m8n8.x2.shared.b16 {%0,%1}, [%2];"    \
                 : "=r"(r0), "=r"(r1) : "r"(ad))

// epoch-based global barrier (monotonic epoch; count self-resets)
__device__ __forceinline__ void gbar() {
    __syncthreads();
    if (threadIdx.x == 0) {
        unsigned e0 = *(volatile unsigned*)&g_epoch;
        __threadfence();
        unsigned old = atomicAdd(&g_cnt, 1u);
        if (old == NBLK - 1) {
            *(volatile unsigned*)&g_cnt = 0u;
            __threadfence();
            atomicAdd(&g_epoch, 1u);
        } else {
            while (*(volatile unsigned*)&g_epoch == e0) { __nanosleep(64); }
        }
        __threadfence();
    }
    __syncthreads();
}

// split-phase barrier: arrive immediately, wait later (overlap work in between)
__device__ __forceinline__ void gbar_arrive(char* smc) {
    __syncthreads();
    if (threadIdx.x == 0) {
        unsigned e0 = *(volatile unsigned*)&g_epoch;
        *(volatile unsigned*)(smc + OFF_EP) = e0;
        __threadfence();
        unsigned old = atomicAdd(&g_cnt, 1u);
        if (old == NBLK - 1) {
            *(volatile unsigned*)&g_cnt = 0u;
            __threadfence();
            atomicAdd(&g_epoch, 1u);
        }
    }
    // no trailing sync: all threads proceed to overlap work
}
__device__ __forceinline__ void gbar_wait(char* smc) {
    if (threadIdx.x == 0) {
        unsigned e0 = *(volatile unsigned*)(smc + OFF_EP);
        while (*(volatile unsigned*)&g_epoch == e0) { __nanosleep(64); }
        __threadfence();
    }
    __syncthreads();
}

// ---------------- finalize from atomic totals: read 2.1KB, compute sc/sh, zero stale ----
__device__ __forceinline__ void finalize_direct(int slot, int zslot,
                                                const float* __restrict__ bng,
                                                const float* __restrict__ bnb,
                                                char* smc, int tid) {
    float* scS = (float*)(smc + OFF_SC);
    float* shS = (float*)(smc + OFF_SH);
    __half2* sc2 = (__half2*)(smc + OFF_SC2);
    __half2* sh2 = (__half2*)(smc + OFF_SH2);
    if (tid < 288) {
        if (tid < H_) {
            float s = g_as[slot * 288 + tid];
            float q = g_aq[slot * 288 + tid];
            float mean = s * (1.f / B_);
            float var = q * (1.f / B_) - mean * mean;
            float inv = rsqrtf(var + EPS);
            float sc = bng[tid] * inv;
            scS[tid] = sc;
            shS[tid] = bnb[tid] - mean * sc;
        } else {
            scS[tid] = 0.f;
            shS[tid] = 0.f;
        }
        g_as[zslot * 288 + tid] = 0.f;
        g_aq[zslot * 288 + tid] = 0.f;
    }
    __syncthreads();
    if (tid < 144) {
        sc2[tid] = __floats2half2_rn(scS[2 * tid], scS[2 * tid + 1]);
        sh2[tid] = __floats2half2_rn(shS[2 * tid], shS[2 * tid + 1]);
    }
    __syncthreads();
}

// ---------------- cp.async chunk issue (64-k chunks, row stride 72 hf) ----------------
__device__ __forceinline__ void issue_chunk(const hf* __restrict__ Ag,
                                            const hf* __restrict__ Wg, int klim,
                                            int nact, char* smc, int bid, int tid,
                                            int ch) {
    hf* As = (hf*)(smc + (ch % 3) * STGB);
    hf* Bs = As + 4608;
    const int gm0 = bid * 64;
#pragma unroll
    for (int l = 0; l < 6; l++) {
        int i = tid + l * THREADS;
        if (i < 512) {
            int row = i >> 3, seg = i & 7, gk = ch * 64 + seg * 8;
            int ok = (gk + 8 <= klim);
            const hf* src = Ag + (size_t)(gm0 + row) * klim + (ok ? gk : 0);
            cpa16(smem_u32(As + row * 72 + seg * 8), src, ok ? 16 : 0);
        } else if (i < 2816) {
            int j = i - 512;
            int n = j >> 3, seg = j & 7, gk = ch * 64 + seg * 8;
            int ok = (gk + 8 <= klim) && (n < nact);
            const hf* src = Wg + (ok ? ((size_t)n * klim + gk) : 0);
            cpa16(smem_u32(Bs + n * 72 + seg * 8), src, ok ? 16 : 0);
        }
    }
    asm volatile("cp.async.commit_group;" ::: "memory");
}

__device__ __forceinline__ void issue2(const hf* Ag, const hf* Wg, int klim, int nact,
                                       char* smc, int bid, int tid) {
    issue_chunk(Ag, Wg, klim, nact, smc, bid, tid, 0);
    issue_chunk(Ag, Wg, klim, nact, smc, bid, tid, 1);
}

// ---------------- GEMM mainloop (chunks 0,1 pre-issued by caller) ----------------
// NC chunks of k=64; the last chunk runs LASTSL k16-slabs (others run 4).
template <int NC, int LASTSL, bool AFFINE>
__device__ __forceinline__ void do_gemm(const hf* __restrict__ Ag,
                                        const hf* __restrict__ Wg, int klim, int nact,
                                        int ntot, int slot, int zslot,
                                        const float* __restrict__ bng,
                                        const float* __restrict__ bnb, char* smc,
                                        int bid, int tid, float acc[2][5][4]) {
    const int lane = tid & 31, w = tid >> 5, wm = w >> 3, wn = w & 7;
    int ntw, cbase;
    if (ntot == 256) {
        ntw = 4;
        cbase = wn * 32;
    } else {
        ntw = (wn < 4) ? 5 : 4;
        cbase = (wn < 4) ? wn * 40 : 160 + (wn - 4) * 32;
    }
    const __half2* sc2 = (const __half2*)(smc + OFF_SC2);
    const __half2* sh2 = (const __half2*)(smc + OFF_SH2);

    if (AFFINE) finalize_direct(slot, zslot, bng, bnb, smc, tid);

    const int jj = lane >> 3, rw = lane & 7;
    const int am_off = (jj & 1) * 8 + rw;
    const int ak_off = (jj >> 1) * 8;

    for (int ch = 0; ch < NC; ch++) {
        if (ch < NC - 1)
            asm volatile("cp.async.wait_group 1;" ::: "memory");
        else
            asm volatile("cp.async.wait_group 0;" ::: "memory");
        __syncthreads();
        if (ch + 2 < NC) issue_chunk(Ag, Wg, klim, nact, smc, bid, tid, ch + 2);

        const hf* As = (const hf*)(smc + (ch % 3) * STGB);
        const hf* Bs = As + 4608;
        const int smax = (ch == NC - 1) ? LASTSL : 4;
#pragma unroll
        for (int sl = 0; sl < 4; sl++) {
            if (sl >= smax) break;
            uint32_t a[2][4];
#pragma unroll
            for (int mt = 0; mt < 2; mt++) {
                const int r = wm * 32 + mt * 16 + am_off;
                LDSM4(a[mt], smem_u32(As + r * 72 + sl * 16 + ak_off));
            }
            if (AFFINE) {
                const int idx = ch * 32 + sl * 8 + (lane & 3);
                const __half2 s0 = sc2[idx], h0 = sh2[idx];
                const __half2 s4 = sc2[idx + 4], h4 = sh2[idx + 4];
                const __half2 z = __floats2half2_rn(0.f, 0.f);
#pragma unroll
                for (int mt = 0; mt < 2; mt++) {
                    __half2 v;
                    v = *(__half2*)&a[mt][0];
                    v = __hmax2(__hfma2(v, s0, h0), z);
                    a[mt][0] = *(uint32_t*)&v;
                    v = *(__half2*)&a[mt][1];
                    v = __hmax2(__hfma2(v, s0, h0), z);
                    a[mt][1] = *(uint32_t*)&v;
                    v = *(__half2*)&a[mt][2];
                    v = __hmax2(__hfma2(v, s4, h4), z);
                    a[mt][2] = *(uint32_t*)&v;
                    v = *(__half2*)&a[mt][3];
                    v = __hmax2(__hfma2(v, s4, h4), z);
                    a[mt][3] = *(uint32_t*)&v;
                }
            }
            uint32_t b[5][2];
#pragma unroll
            for (int p = 0; p < 2; p++) {
                const int ntp = p * 2 + (jj >> 1);
                const int kb = (jj & 1) * 8;
                const int rowb = cbase + ntp * 8 + rw;
                uint32_t r4[4];
                LDSM4(r4, smem_u32(Bs + rowb * 72 + sl * 16 + kb));
                b[2 * p][0] = r4[0];
                b[2 * p][1] = r4[1];
                b[2 * p + 1][0] = r4[2];
                b[2 * p + 1][1] = r4[3];
            }
            if (ntw == 5) {
                const int kb = (jj & 1) * 8;
                const int rowb = cbase + 32 + rw;
                LDSM2(b[4][0], b[4][1], smem_u32(Bs + rowb * 72 + sl * 16 + kb));
            }
#pragma unroll
            for (int nt = 0; nt < 5; nt++) {
                if (nt < ntw) {
                    MMAH(acc[0][nt], a[0], b[nt][0], b[nt][1]);
                    MMAH(acc[1][nt], a[1], b[nt][0], b[nt][1]);
                }
            }
        }
    }
    __syncthreads();
}

// ---------------- epilogue: bias, hf Y store, column stats -> atomic slot ----------------
__device__ __forceinline__ void epi_stats(float acc[2][5][4], const float* __restrict__ bias,
                                          hf* __restrict__ Yg, int N_ACT, int slot,
                                          char* smc, int bid, int tid) {
    const int lane = tid & 31, w = tid >> 5, wm = w >> 3, wn = w & 7;
    const int ntw = (wn < 4) ? 5 : 4;
    const int cbase = (wn < 4) ? wn * 40 : 160 + (wn - 4) * 32;
    float* ps = (float*)(smc + OFF_RED);
    float* pq = ps + 640;
#pragma unroll
    for (int nt = 0; nt < 5; nt++) {
        if (nt >= ntw) continue;
        const int c0 = cbase + nt * 8 + 2 * (lane & 3);
        float b0 = 0.f, b1 = 0.f;
        if (c0 < N_ACT) { b0 = bias[c0]; b1 = bias[c0 + 1]; }
        float s0 = 0.f, s1 = 0.f, q0 = 0.f, q1 = 0.f;
#pragma unroll
        for (int mt = 0; mt < 2; mt++) {
            const int rbase = bid * 64 + wm * 32 + mt * 16 + (lane >> 2);
#pragma unroll
            for (int rs = 0; rs < 2; rs++) {
                float y0 = acc[mt][nt][rs * 2 + 0] + b0;
                float y1 = acc[mt][nt][rs * 2 + 1] + b1;
                const int row = rbase + rs * 8;
                if (c0 < N_ACT)
                    *(uint32_t*)(Yg + (size_t)row * HP + c0) = packhf(y0, y1);
                else if (c0 < HP)
                    *(uint32_t*)(Yg + (size_t)row * HP + c0) = 0u;
                s0 += y0; s1 += y1;
                q0 += y0 * y0; q1 += y1 * y1;
            }
        }
#pragma unroll
        for (int m = 4; m <= 16; m <<= 1) {
            s0 += __shfl_xor_sync(~0u, s0, m);
            s1 += __shfl_xor_sync(~0u, s1, m);
            q0 += __shfl_xor_sync(~0u, q0, m);
            q1 += __shfl_xor_sync(~0u, q1, m);
        }
        if (lane < 4) {
            ps[w * 40 + nt * 8 + 2 * lane] = s0;
            ps[w * 40 + nt * 8 + 2 * lane + 1] = s1;
            pq[w * 40 + nt * 8 + 2 * lane] = q0;
            pq[w * 40 + nt * 8 + 2 * lane + 1] = q1;
        }
    }
    __syncthreads();
    if (tid < H_) {
        const int n = tid;
        const int wn2 = (n < 160) ? (n / 40) : (4 + (n - 160) / 32);
        const int loc = (n < 160) ? (n % 40) : ((n - 160) % 32);
        float s = ps[wn2 * 40 + loc] + ps[(8 + wn2) * 40 + loc];
        float q = pq[wn2 * 40 + loc] + pq[(8 + wn2) * 40 + loc];
        atomicAdd(&g_as[slot * 288 + n], s);
        atomicAdd(&g_aq[slot * 288 + n], q);
    }
    __syncthreads();
}

// ---------------- L3 epilogue fused with SDE update (N=256) ----------------
__device__ __forceinline__ void epi_update(float acc[2][5][4], const float* __restrict__ b3,
                                           const float* __restrict__ xi_t,
                                           const float* __restrict__ xsrc,
                                           float* __restrict__ xdst,
                                           hf* __restrict__ xh, float ht, char* smc,
                                           int bid, int tid) {
    const int lane = tid & 31, w = tid >> 5, wm = w >> 3, wn = w & 7;
    const int cbase = wn * 32;
    const float sq = sqrtf(ht);
    float fa[2][2] = {}, da[2][2] = {};
#pragma unroll
    for (int nt = 0; nt < 4; nt++) {
        const int c0 = cbase + nt * 8 + 2 * (lane & 3);
        const float b0 = b3[c0], b1 = b3[c0 + 1];
#pragma unroll
        for (int mt = 0; mt < 2; mt++) {
#pragma unroll
            for (int rs = 0; rs < 2; rs++) {
                const int row = bid * 64 + wm * 32 + mt * 16 + (lane >> 2) + rs * 8;
                float gg0 = acc[mt][nt][rs * 2 + 0] + b0;
                float gg1 = acc[mt][nt][rs * 2 + 1] + b1;
                float2 xi2 = *(const float2*)(xi_t + (size_t)row * 256 + c0);
                float2 xs2 = *(const float2*)(xsrc + (size_t)row * 256 + c0);
                float n0 = sq * xi2.x, n1 = sq * xi2.y;
                fa[mt][rs] += gg0 * gg0 + gg1 * gg1;
                da[mt][rs] += gg0 * n0 + gg1 * n1;
                float xn0 = xs2.x - gg0 * ht + n0;
                float xn1 = xs2.y - gg1 * ht + n1;
                *(float2*)(xdst + (size_t)row * 256 + c0) = make_float2(xn0, xn1);
                if (xh)
                    *(uint32_t*)(xh + (size_t)row * 256 + c0) = packhf(xn0, xn1);
            }
        }
    }
#pragma unroll
    for (int m = 1; m <= 2; m <<= 1) {
#pragma unroll
        for (int mt = 0; mt < 2; mt++)
#pragma unroll
            for (int rs = 0; rs < 2; rs++) {
                fa[mt][rs] += __shfl_xor_sync(~0u, fa[mt][rs], m);
                da[mt][rs] += __shfl_xor_sync(~0u, da[mt][rs], m);
            }
    }
    float* rf = (float*)(smc + OFF_RED);
    float* rd = rf + 512;
    if ((lane & 3) == 0) {
#pragma unroll
        for (int mt = 0; mt < 2; mt++)
#pragma unroll
            for (int rs = 0; rs < 2; rs++) {
                int rl = wm * 32 + mt * 16 + (lane >> 2) + rs * 8;
                rf[wn * 64 + rl] = fa[mt][rs];
                rd[wn * 64 + rl] = da[mt][rs];
            }
    }
    __syncthreads();
    float* vs = (float*)(smc + OFF_VS);
    if (tid < 64) {
        float F = 0.f, Dt = 0.f;
#pragma unroll
        for (int j = 0; j < 8; j++) {
            F += rf[j * 64 + tid];
            Dt += rd[j * 64 + tid];
        }
        vs[tid] += -F * ht + Dt;
    }
    __syncthreads();
}

// ---------------- v0 tail ----------------
__device__ __forceinline__ void v3_part(const hf* __restrict__ h2,
                                        const float* __restrict__ vW3,
                                        const float* __restrict__ vb3, char* smc,
                                        int bid, int tid) {
    const int lane = tid & 31, w = tid >> 5;
    const float* scS = (const float*)(smc + OFF_SC);
    const float* shS = (const float*)(smc + OFF_SH);
    float* yv = (float*)(smc + OFF_RED);
    for (int i = 0; i < 4; i++) {
        int row = w * 4 + i;
        size_t base = (size_t)(bid * 64 + row) * HP;
        float s = 0.f;
        for (int k = lane; k < H_; k += 32) {
            float hv = __half2float(h2[base + k]);
            float a2 = fmaxf(fmaf(hv, scS[k], shS[k]), 0.f);
            s = fmaf(a2, vW3[k], s);
        }
#pragma unroll
        for (int m = 16; m > 0; m >>= 1) s += __shfl_xor_sync(~0u, s, m);
        if (lane == 0) yv[row] = s + vb3[0];
    }
    __syncthreads();
    if (tid == 0) {
        float s = 0.f, q = 0.f;
        for (int i = 0; i < 64; i++) {
            float t = yv[i];
            s += t;
            q = fmaf(t, t, q);
        }
        g_ps0[bid] = s;
        g_pq0[bid] = q;
    }
    __syncthreads();
}

__device__ __forceinline__ void v0_final(const float* __restrict__ vg3,
                                         const float* __restrict__ vbe3, char* smc,
                                         int tid) {
    float* yv = (float*)(smc + OFF_RED);
    float* bc = (float*)(smc + OFF_BC);
    float* vs = (float*)(smc + OFF_VS);
    if (tid == 0) {
        float s = 0.f, q = 0.f;
        for (int b = 0; b < NBLK; b++) { s += g_ps0[b]; q += g_pq0[b]; }
        float m = s * (1.f / B_);
        float var = q * (1.f / B_) - m * m;
        float inv = rsqrtf(var + EPS);
        float sc = vg3[0] * inv;
        bc[0] = sc;
        bc[1] = vbe3[0] - m * sc;
    }
    __syncthreads();
    if (tid < 64) vs[tid] = fmaxf(fmaf(yv[tid], bc[0], bc[1]), 0.f);
    __syncthreads();
}

// ---------------- the persistent mega-kernel ----------------
__global__ void __launch_bounds__(THREADS, 1) mega(
    const float* __restrict__ x, const float* __restrict__ xi,
    const float* __restrict__ tg, const float* __restrict__ W1,
    const float* __restrict__ b1, const float* __restrict__ g1,
    const float* __restrict__ be1, const float* __restrict__ W2,
    const float* __restrict__ b2, const float* __restrict__ g2,
    const float* __restrict__ be2, const float* __restrict__ W3,
    const float* __restrict__ b3, const float* __restrict__ vW1,
    const float* __restrict__ vb1, const float* __restrict__ vg1,
    const float* __restrict__ vbe1, const float* __restrict__ vW2,
    const float* __restrict__ vb2, const float* __restrict__ vg2,
    const float* __restrict__ vbe2, const float* __restrict__ vW3,
    const float* __restrict__ vb3, const float* __restrict__ vg3,
    const float* __restrict__ vbe3, float* __restrict__ out) {
    extern __shared__ char smc[];
    const int bid = blockIdx.x, tid = threadIdx.x;

    // ---- phase 0: convert weights + x to fp16; zero atomic slots (once) ----
    {
        const int gt = bid * THREADS + tid, gs = NBLK * THREADS;
        for (int i = gt; i < T_ * H_ * D_; i += gs)
            g_w[GW1 + i] = __float2half(W1[i]);
        for (int i = gt; i < T_ * H_ * HP; i += gs) {
            int r = i / HP, k = i - r * HP;
            g_w[GW2 + i] = (k < H_) ? __float2half(W2[r * H_ + k]) : __float2half(0.f);
        }
        for (int i = gt; i < T_ * D_ * HP; i += gs) {
            int r = i / HP, k = i - r * HP;
            g_w[GW3 + i] = (k < H_) ? __float2half(W3[r * H_ + k]) : __float2half(0.f);
        }
        for (int i = gt; i < H_ * D_; i += gs)
            g_w[GVW1 + i] = __float2half(vW1[i]);
        for (int i = gt; i < H_ * HP; i += gs) {
            int r = i / HP, k = i - r * HP;
            g_w[GVW2 + i] = (k < H_) ? __float2half(vW2[r * H_ + k]) : __float2half(0.f);
        }
        for (int i = gt; i < B_ * D_; i += gs) g_xh[i] = __float2half(x[i]);
        for (int i = gt; i < 3 * 288; i += gs) {
            g_as[i] = 0.f;
            g_aq[i] = 0.f;
        }
    }
    gbar();

    int bn = 0;  // vector-BN counter (slot = bn % 3)

    // ---- v0 network ----
    issue2(g_xh, g_w + GVW1, 256, 266, smc, bid, tid);
    {
        float acc[2][5][4] = {};
        do_gemm<4, 4, false>(g_xh, g_w + GVW1, 256, 266, 288, 0, 0, nullptr, nullptr,
                             smc, bid, tid, acc);
        epi_stats(acc, vb1, g_h1, 266, bn % 3, smc, bid, tid);
    }
    gbar_arrive(smc);
    issue2(g_h1, g_w + GVW2, 272, 266, smc, bid, tid);
    gbar_wait(smc);
    {
        float acc[2][5][4] = {};
        do_gemm<5, 1, true>(g_h1, g_w + GVW2, 272, 266, 288, bn % 3, (bn + 2) % 3, vg1,
                            vbe1, smc, bid, tid, acc);
        bn++;
        epi_stats(acc, vb2, g_h2, 266, bn % 3, smc, bid, tid);
    }
    gbar();
    finalize_direct(bn % 3, (bn + 2) % 3, vg2, vbe2, smc, tid);
    bn++;
    v3_part(g_h2, vW3, vb3, smc, bid, tid);
    gbar();
    v0_final(vg3, vbe3, smc, tid);

    issue2(g_xh, g_w + GW1, 256, 266, smc, bid, tid);

    // ---- time-stepping scan ----
    for (int t = 0; t < T_; t++) {
        const float* xsrc = (t == 0) ? x : g_x;
        const hf* W1t = g_w + GW1 + (size_t)t * H_ * D_;
        const hf* W2t = g_w + GW2 + (size_t)t * H_ * HP;
        const hf* W3t = g_w + GW3 + (size_t)t * D_ * HP;
        const float* b1t = b1 + (size_t)t * H_;
        const float* g1t = g1 + (size_t)t * H_;
        const float* be1t = be1 + (size_t)t * H_;
        const float* b2t = b2 + (size_t)t * H_;
        const float* g2t = g2 + (size_t)t * H_;
        const float* be2t = be2 + (size_t)t * H_;
        const float* b3t = b3 + (size_t)t * D_;
        const float* xit = xi + (size_t)t * B_ * D_;

        {
            float acc[2][5][4] = {};
            do_gemm<4, 4, false>(g_xh, W1t, 256, 266, 288, 0, 0, nullptr, nullptr, smc,
                                 bid, tid, acc);
            epi_stats(acc, b1t, g_h1, 266, bn % 3, smc, bid, tid);
        }
        gbar_arrive(smc);
        issue2(g_h1, W2t, 272, 266, smc, bid, tid);
        gbar_wait(smc);
        {
            float acc[2][5][4] = {};
            do_gemm<5, 1, true>(g_h1, W2t, 272, 266, 288, bn % 3, (bn + 2) % 3, g1t,
                                be1t, smc, bid, tid, acc);
            bn++;
            epi_stats(acc, b2t, g_h2, 266, bn % 3, smc, bid, tid);
        }
        gbar_arrive(smc);
        issue2(g_h2, W3t, 272, 256, smc, bid, tid);
        gbar_wait(smc);
        {
            float acc[2][5][4] = {};
            do_gemm<5, 1, true>(g_h2, W3t, 272, 256, 256, bn % 3, (bn + 2) % 3, g2t,
                                be2t, smc, bid, tid, acc);
            bn++;
            float ht = tg[t + 1] - tg[t];
            float* xdst = (t == T_ - 1) ? (out + B_) : g_x;
            hf* xh = (t == T_ - 1) ? nullptr : g_xh;
            epi_update(acc, b3t, xit, xsrc, xdst, xh, ht, smc, bid, tid);
        }
        if (t + 1 < T_) {
            issue2(g_xh, g_w + GW1 + (size_t)(t + 1) * H_ * D_, 256, 266, smc, bid, tid);
        }
    }

    // ---- output v ----
    if (tid < 64) out[bid * 64 + tid] = ((float*)(smc + OFF_VS))[tid];
}

// ---------------- host ----------------
extern "C" void kernel_launch(void* const* d_in, const int* in_sizes, int n_in,
                              void* d_out, int out_size) {
    const float* x    = (const float*)d_in[0];
    const float* xi   = (const float*)d_in[1];
    const float* tg   = (const float*)d_in[2];
    const float* W1   = (const float*)d_in[3];
    const float* b1   = (const float*)d_in[4];
    const float* g1   = (const float*)d_in[5];
    const float* be1  = (const float*)d_in[6];
    const float* W2   = (const float*)d_in[7];
    const float* b2   = (const float*)d_in[8];
    const float* g2   = (const float*)d_in[9];
    const float* be2  = (const float*)d_in[10];
    const float* W3   = (const float*)d_in[11];
    const float* b3   = (const float*)d_in[12];
    const float* vW1  = (const float*)d_in[13];
    const float* vb1  = (const float*)d_in[14];
    const float* vg1  = (const float*)d_in[15];
    const float* vbe1 = (const float*)d_in[16];
    const float* vW2  = (const float*)d_in[17];
    const float* vb2  = (const float*)d_in[18];
    const float* vg2  = (const float*)d_in[19];
    const float* vbe2 = (const float*)d_in[20];
    const float* vW3  = (const float*)d_in[21];
    const float* vb3  = (const float*)d_in[22];
    const float* vg3  = (const float*)d_in[23];
    const float* vbe3 = (const float*)d_in[24];

    cudaFuncSetAttribute(mega, cudaFuncAttributeMaxDynamicSharedMemorySize, SMEM_BYTES);
    mega<<<NBLK, THREADS, SMEM_BYTES>>>(x, xi, tg, W1, b1, g1, be1, W2, b2, g2, be2,
                                        W3, b3, vW1, vb1, vg1, vbe1, vW2, vb2, vg2,
                                        vbe2, vW3, vb3, vg3, vbe3, (float*)d_out);
}

// round 17
// speedup vs baseline: 1.0579x; 1.0281x over previous
#include <cuda_runtime.h>
#include <cuda_fp16.h>
#include <math.h>
#include <stdint.h>

#define B_ 8192
#define D_ 256
#define H_ 266
#define HP 272
#define T_ 20
#define NBLK 128
#define THREADS 512
#define EPS 1e-5f

typedef __half hf;

// ---------------- persistent state (no allocation allowed) ----------------
__device__ float g_x[B_ * D_];
__device__ hf g_xh[B_ * D_];
__device__ hf g_h1[B_ * HP];
__device__ hf g_h2[B_ * HP];
__device__ float g_as[3 * 288];   // rotating atomic column-sum slots
__device__ float g_aq[3 * 288];
__device__ float g_ps0[NBLK];
__device__ float g_pq0[NBLK];
__device__ unsigned g_cnt;
__device__ unsigned g_epoch;

// fp16 weights, K-padded so every row is 16B aligned
#define GW1 0                 // T*266 rows, stride 256
#define GW2 1361920           // T*266 rows, stride 272
#define GW3 2808960           // T*256 rows, stride 272
#define GVW1 4201600          // 266 rows, stride 256
#define GVW2 4269696          // 266 rows, stride 272
#define GWTOT 4342048
__device__ hf g_w[GWTOT];

// ---------------- smem layout (byte offsets) ----------------
// stage: A 64x88 hf (11264B) + B 288x88 hf (50688B) = 61952B; 3 stages
#define STGB 61952
#define OFF_SC 185856   // float[288]
#define OFF_SH 187008   // float[288]
#define OFF_SC2 188160  // half2[144]
#define OFF_SH2 188736  // half2[144]
#define OFF_RED 189312  // float[1280]
#define OFF_VS 194432   // float[64]
#define OFF_BC 194688   // float[8]
#define SMEM_BYTES 194720

// ---------------- low-level helpers ----------------
__device__ __forceinline__ uint32_t smem_u32(const void* p) {
    uint32_t a;
    asm("{ .reg .u64 t; cvta.to.shared.u64 t, %1; cvt.u32.u64 %0, t; }" : "=r"(a) : "l"(p));
    return a;
}
__device__ __forceinline__ void cpa16(uint32_t dst, const void* src, int sz) {
    asm volatile("cp.async.cg.shared.global [%0], [%1], 16, %2;" :: "r"(dst), "l"(src),
                 "r"(sz));
}
__device__ __forceinline__ uint32_t packhf(float a, float b) {
    __half2 t = __floats2half2_rn(a, b);
    return *(uint32_t*)&t;
}
#define MMAH(d, a, b0, b1)                                                    \
    asm volatile(                                                             \
        "mma.sync.aligned.m16n8k16.row.col.f32.f16.f16.f32 "                  \
        "{%0,%1,%2,%3},{%4,%5,%6,%7},{%8,%9},{%0,%1,%2,%3};"                  \
        : "+f"(d[0]), "+f"(d[1]), "+f"(d[2]), "+f"(d[3])                      \
        : "r"(a[0]), "r"(a[1]), "r"(a[2]), "r"(a[3]), "r"(b0), "r"(b1))
#define LDSM4(r, ad)                                                          \
    asm volatile("ldmatrix.sync.aligned.m8n8.x4.shared.b16 {%0,%1,%2,%3}, [%4];" \
                 : "=r"((r)[0]), "=r"((r)[1]), "=r"((r)[2]), "=r"((r)[3])     \
                 : "r"(ad))
#define LDSM2(r0, r1, ad)                                                     \
    asm volatile("ldmatrix.sync.aligned.m8n8.x2.shared.b16 {%0,%1}, [%2];"    \
                 : "=r"(r0), "=r"(r1) : "r"(ad))

// epoch-based global barrier (monotonic epoch; count self-resets)
__device__ __forceinline__ void gbar() {
    __syncthreads();
    if (threadIdx.x == 0) {
        unsigned e0 = *(volatile unsigned*)&g_epoch;
        __threadfence();
        unsigned old = atomicAdd(&g_cnt, 1u);
        if (old == NBLK - 1) {
            *(volatile unsigned*)&g_cnt = 0u;
            __threadfence();
            atomicAdd(&g_epoch, 1u);
        } else {
            while (*(volatile unsigned*)&g_epoch == e0) { __nanosleep(64); }
        }
        __threadfence();
    }
    __syncthreads();
}

// ---------------- finalize from atomic totals: read 2.1KB, compute sc/sh, zero stale ----
__device__ __forceinline__ void finalize_direct(int slot, int zslot,
                                                const float* __restrict__ bng,
                                                const float* __restrict__ bnb,
                                                char* smc, int tid) {
    float* scS = (float*)(smc + OFF_SC);
    float* shS = (float*)(smc + OFF_SH);
    __half2* sc2 = (__half2*)(smc + OFF_SC2);
    __half2* sh2 = (__half2*)(smc + OFF_SH2);
    if (tid < 288) {
        if (tid < H_) {
            float s = g_as[slot * 288 + tid];
            float q = g_aq[slot * 288 + tid];
            float mean = s * (1.f / B_);
            float var = q * (1.f / B_) - mean * mean;
            float inv = rsqrtf(var + EPS);
            float sc = bng[tid] * inv;
            scS[tid] = sc;
            shS[tid] = bnb[tid] - mean * sc;
        } else {
            scS[tid] = 0.f;
            shS[tid] = 0.f;
        }
        g_as[zslot * 288 + tid] = 0.f;
        g_aq[zslot * 288 + tid] = 0.f;
    }
    __syncthreads();
    if (tid < 144) {
        sc2[tid] = __floats2half2_rn(scS[2 * tid], scS[2 * tid + 1]);
        sh2[tid] = __floats2half2_rn(shS[2 * tid], shS[2 * tid + 1]);
    }
    __syncthreads();
}

// ---------------- cp.async chunk issue (row stride 88 hf; SEGS 8-halves per row) -------
// All segments in-K by construction; B rows [nact,288) zero-filled via sz=0.
template <int SEGS>
__device__ __forceinline__ void issue_chunk(const hf* __restrict__ Ag,
                                            const hf* __restrict__ Wg, int klim,
                                            int nact, char* smc, int bid, int tid,
                                            int ch) {
    hf* As = (hf*)(smc + (ch % 3) * STGB);
    hf* Bs = As + 5632;
    const int gm0 = bid * 64;
    const int koff = ch * 64;
    constexpr int ACNT = 64 * SEGS;
    constexpr int TOT = ACNT + 288 * SEGS;
#pragma unroll
    for (int l = 0; l < (TOT + THREADS - 1) / THREADS; l++) {
        int i = tid + l * THREADS;
        if (i < ACNT) {
            int row = i / SEGS, seg = i - row * SEGS, gk = koff + seg * 8;
            cpa16(smem_u32(As + row * 88 + seg * 8),
                  Ag + (size_t)(gm0 + row) * klim + gk, 16);
        } else if (i < TOT) {
            int j = i - ACNT;
            int n = j / SEGS, seg = j - n * SEGS, gk = koff + seg * 8;
            int ok = (n < nact);
            const hf* src = Wg + (ok ? ((size_t)n * klim + gk) : 0);
            cpa16(smem_u32(Bs + n * 88 + seg * 8), src, ok ? 16 : 0);
        }
    }
    asm volatile("cp.async.commit_group;" ::: "memory");
}

__device__ __forceinline__ void issue2(const hf* Ag, const hf* Wg, int klim, int nact,
                                       char* smc, int bid, int tid) {
    issue_chunk<8>(Ag, Wg, klim, nact, smc, bid, tid, 0);
    issue_chunk<8>(Ag, Wg, klim, nact, smc, bid, tid, 1);
}

// ---------------- GEMM mainloop (chunks 0,1 pre-issued by caller) ----------------
// 4 chunks {64,64,64,LASTSL*16}; uniform NC=4.
template <int LASTSL, bool AFFINE>
__device__ __forceinline__ void do_gemm(const hf* __restrict__ Ag,
                                        const hf* __restrict__ Wg, int klim, int nact,
                                        int ntot, int slot, int zslot,
                                        const float* __restrict__ bng,
                                        const float* __restrict__ bnb, char* smc,
                                        int bid, int tid, float acc[2][5][4]) {
    const int lane = tid & 31, w = tid >> 5, wm = w >> 3, wn = w & 7;
    int ntw, cbase;
    if (ntot == 256) {
        ntw = 4;
        cbase = wn * 32;
    } else {
        ntw = (wn < 4) ? 5 : 4;
        cbase = (wn < 4) ? wn * 40 : 160 + (wn - 4) * 32;
    }
    const __half2* sc2 = (const __half2*)(smc + OFF_SC2);
    const __half2* sh2 = (const __half2*)(smc + OFF_SH2);

    if (AFFINE) finalize_direct(slot, zslot, bng, bnb, smc, tid);

    const int jj = lane >> 3, rw = lane & 7;
    const int am_off = (jj & 1) * 8 + rw;
    const int ak_off = (jj >> 1) * 8;

    for (int ch = 0; ch < 4; ch++) {
        if (ch < 3)
            asm volatile("cp.async.wait_group 1;" ::: "memory");
        else
            asm volatile("cp.async.wait_group 0;" ::: "memory");
        __syncthreads();
        if (ch == 0)
            issue_chunk<8>(Ag, Wg, klim, nact, smc, bid, tid, 2);
        else if (ch == 1)
            issue_chunk<LASTSL * 2>(Ag, Wg, klim, nact, smc, bid, tid, 3);

        const hf* As = (const hf*)(smc + (ch % 3) * STGB);
        const hf* Bs = As + 5632;
        const int smax = (ch == 3) ? LASTSL : 4;
#pragma unroll
        for (int sl = 0; sl < 5; sl++) {
            if (sl >= smax) break;
            uint32_t a[2][4];
#pragma unroll
            for (int mt = 0; mt < 2; mt++) {
                const int r = wm * 32 + mt * 16 + am_off;
                LDSM4(a[mt], smem_u32(As + r * 88 + sl * 16 + ak_off));
            }
            if (AFFINE) {
                const int idx = ch * 32 + sl * 8 + (lane & 3);
                const __half2 s0 = sc2[idx], h0 = sh2[idx];
                const __half2 s4 = sc2[idx + 4], h4 = sh2[idx + 4];
                const __half2 z = __floats2half2_rn(0.f, 0.f);
#pragma unroll
                for (int mt = 0; mt < 2; mt++) {
                    __half2 v;
                    v = *(__half2*)&a[mt][0];
                    v = __hmax2(__hfma2(v, s0, h0), z);
                    a[mt][0] = *(uint32_t*)&v;
                    v = *(__half2*)&a[mt][1];
                    v = __hmax2(__hfma2(v, s0, h0), z);
                    a[mt][1] = *(uint32_t*)&v;
                    v = *(__half2*)&a[mt][2];
                    v = __hmax2(__hfma2(v, s4, h4), z);
                    a[mt][2] = *(uint32_t*)&v;
                    v = *(__half2*)&a[mt][3];
                    v = __hmax2(__hfma2(v, s4, h4), z);
                    a[mt][3] = *(uint32_t*)&v;
                }
            }
            uint32_t b[5][2];
#pragma unroll
            for (int p = 0; p < 2; p++) {
                const int ntp = p * 2 + (jj >> 1);
                const int kb = (jj & 1) * 8;
                const int rowb = cbase + ntp * 8 + rw;
                uint32_t r4[4];
                LDSM4(r4, smem_u32(Bs + rowb * 88 + sl * 16 + kb));
                b[2 * p][0] = r4[0];
                b[2 * p][1] = r4[1];
                b[2 * p + 1][0] = r4[2];
                b[2 * p + 1][1] = r4[3];
            }
            if (ntw == 5) {
                const int kb = (jj & 1) * 8;
                const int rowb = cbase + 32 + rw;
                LDSM2(b[4][0], b[4][1], smem_u32(Bs + rowb * 88 + sl * 16 + kb));
            }
#pragma unroll
            for (int nt = 0; nt < 5; nt++) {
                if (nt < ntw) {
                    MMAH(acc[0][nt], a[0], b[nt][0], b[nt][1]);
                    MMAH(acc[1][nt], a[1], b[nt][0], b[nt][1]);
                }
            }
        }
    }
    __syncthreads();
}

// ---------------- epilogue: bias, hf Y store, column stats -> atomic slot ----------------
// Pad columns [266,272) of Yg are pre-zeroed once at init; only real cols stored here.
__device__ __forceinline__ void epi_stats(float acc[2][5][4], const float* __restrict__ bias,
                                          hf* __restrict__ Yg, int N_ACT, int slot,
                                          char* smc, int bid, int tid) {
    const int lane = tid & 31, w = tid >> 5, wm = w >> 3, wn = w & 7;
    const int ntw = (wn < 4) ? 5 : 4;
    const int cbase = (wn < 4) ? wn * 40 : 160 + (wn - 4) * 32;
    float* ps = (float*)(smc + OFF_RED);
    float* pq = ps + 640;
#pragma unroll
    for (int nt = 0; nt < 5; nt++) {
        if (nt >= ntw) continue;
        const int c0 = cbase + nt * 8 + 2 * (lane & 3);
        float b0 = 0.f, b1 = 0.f;
        if (c0 < N_ACT) { b0 = bias[c0]; b1 = bias[c0 + 1]; }
        float s0 = 0.f, s1 = 0.f, q0 = 0.f, q1 = 0.f;
#pragma unroll
        for (int mt = 0; mt < 2; mt++) {
            const int rbase = bid * 64 + wm * 32 + mt * 16 + (lane >> 2);
#pragma unroll
            for (int rs = 0; rs < 2; rs++) {
                float y0 = acc[mt][nt][rs * 2 + 0] + b0;
                float y1 = acc[mt][nt][rs * 2 + 1] + b1;
                const int row = rbase + rs * 8;
                if (c0 < N_ACT)
                    *(uint32_t*)(Yg + (size_t)row * HP + c0) = packhf(y0, y1);
                s0 += y0; s1 += y1;
                q0 += y0 * y0; q1 += y1 * y1;
            }
        }
#pragma unroll
        for (int m = 4; m <= 16; m <<= 1) {
            s0 += __shfl_xor_sync(~0u, s0, m);
            s1 += __shfl_xor_sync(~0u, s1, m);
            q0 += __shfl_xor_sync(~0u, q0, m);
            q1 += __shfl_xor_sync(~0u, q1, m);
        }
        if (lane < 4) {
            ps[w * 40 + nt * 8 + 2 * lane] = s0;
            ps[w * 40 + nt * 8 + 2 * lane + 1] = s1;
            pq[w * 40 + nt * 8 + 2 * lane] = q0;
            pq[w * 40 + nt * 8 + 2 * lane + 1] = q1;
        }
    }
    __syncthreads();
    if (tid < H_) {
        const int n = tid;
        const int wn2 = (n < 160) ? (n / 40) : (4 + (n - 160) / 32);
        const int loc = (n < 160) ? (n % 40) : ((n - 160) % 32);
        float s = ps[wn2 * 40 + loc] + ps[(8 + wn2) * 40 + loc];
        float q = pq[wn2 * 40 + loc] + pq[(8 + wn2) * 40 + loc];
        atomicAdd(&g_as[slot * 288 + n], s);
        atomicAdd(&g_aq[slot * 288 + n], q);
    }
    __syncthreads();
}

// ---------------- L3 epilogue fused with SDE update (N=256) ----------------
__device__ __forceinline__ void epi_update(float acc[2][5][4], const float* __restrict__ b3,
                                           const float* __restrict__ xi_t,
                                           const float* __restrict__ xsrc,
                                           float* __restrict__ xdst,
                                           hf* __restrict__ xh, float ht, char* smc,
                                           int bid, int tid) {
    const int lane = tid & 31, w = tid >> 5, wm = w >> 3, wn = w & 7;
    const int cbase = wn * 32;
    const float sq = sqrtf(ht);
    float fa[2][2] = {}, da[2][2] = {};
#pragma unroll
    for (int nt = 0; nt < 4; nt++) {
        const int c0 = cbase + nt * 8 + 2 * (lane & 3);
        const float b0 = b3[c0], b1 = b3[c0 + 1];
#pragma unroll
        for (int mt = 0; mt < 2; mt++) {
#pragma unroll
            for (int rs = 0; rs < 2; rs++) {
                const int row = bid * 64 + wm * 32 + mt * 16 + (lane >> 2) + rs * 8;
                float gg0 = acc[mt][nt][rs * 2 + 0] + b0;
                float gg1 = acc[mt][nt][rs * 2 + 1] + b1;
                float2 xi2 = *(const float2*)(xi_t + (size_t)row * 256 + c0);
                float2 xs2 = *(const float2*)(xsrc + (size_t)row * 256 + c0);
                float n0 = sq * xi2.x, n1 = sq * xi2.y;
                fa[mt][rs] += gg0 * gg0 + gg1 * gg1;
                da[mt][rs] += gg0 * n0 + gg1 * n1;
                float xn0 = xs2.x - gg0 * ht + n0;
                float xn1 = xs2.y - gg1 * ht + n1;
                *(float2*)(xdst + (size_t)row * 256 + c0) = make_float2(xn0, xn1);
                if (xh)
                    *(uint32_t*)(xh + (size_t)row * 256 + c0) = packhf(xn0, xn1);
            }
        }
    }
#pragma unroll
    for (int m = 1; m <= 2; m <<= 1) {
#pragma unroll
        for (int mt = 0; mt < 2; mt++)
#pragma unroll
            for (int rs = 0; rs < 2; rs++) {
                fa[mt][rs] += __shfl_xor_sync(~0u, fa[mt][rs], m);
                da[mt][rs] += __shfl_xor_sync(~0u, da[mt][rs], m);
            }
    }
    float* rf = (float*)(smc + OFF_RED);
    float* rd = rf + 512;
    if ((lane & 3) == 0) {
#pragma unroll
        for (int mt = 0; mt < 2; mt++)
#pragma unroll
            for (int rs = 0; rs < 2; rs++) {
                int rl = wm * 32 + mt * 16 + (lane >> 2) + rs * 8;
                rf[wn * 64 + rl] = fa[mt][rs];
                rd[wn * 64 + rl] = da[mt][rs];
            }
    }
    __syncthreads();
    float* vs = (float*)(smc + OFF_VS);
    if (tid < 64) {
        float F = 0.f, Dt = 0.f;
#pragma unroll
        for (int j = 0; j < 8; j++) {
            F += rf[j * 64 + tid];
            Dt += rd[j * 64 + tid];
        }
        vs[tid] += -F * ht + Dt;
    }
    __syncthreads();
}

// ---------------- v0 tail ----------------
__device__ __forceinline__ void v3_part(const hf* __restrict__ h2,
                                        const float* __restrict__ vW3,
                                        const float* __restrict__ vb3, char* smc,
                                        int bid, int tid) {
    const int lane = tid & 31, w = tid >> 5;
    const float* scS = (const float*)(smc + OFF_SC);
    const float* shS = (const float*)(smc + OFF_SH);
    float* yv = (float*)(smc + OFF_RED);
    for (int i = 0; i < 4; i++) {
        int row = w * 4 + i;
        size_t base = (size_t)(bid * 64 + row) * HP;
        float s = 0.f;
        for (int k = lane; k < H_; k += 32) {
            float hv = __half2float(h2[base + k]);
            float a2 = fmaxf(fmaf(hv, scS[k], shS[k]), 0.f);
            s = fmaf(a2, vW3[k], s);
        }
#pragma unroll
        for (int m = 16; m > 0; m >>= 1) s += __shfl_xor_sync(~0u, s, m);
        if (lane == 0) yv[row] = s + vb3[0];
    }
    __syncthreads();
    if (tid == 0) {
        float s = 0.f, q = 0.f;
        for (int i = 0; i < 64; i++) {
            float t = yv[i];
            s += t;
            q = fmaf(t, t, q);
        }
        g_ps0[bid] = s;
        g_pq0[bid] = q;
    }
    __syncthreads();
}

__device__ __forceinline__ void v0_final(const float* __restrict__ vg3,
                                         const float* __restrict__ vbe3, char* smc,
                                         int tid) {
    float* yv = (float*)(smc + OFF_RED);
    float* bc = (float*)(smc + OFF_BC);
    float* vs = (float*)(smc + OFF_VS);
    if (tid == 0) {
        float s = 0.f, q = 0.f;
        for (int b = 0; b < NBLK; b++) { s += g_ps0[b]; q += g_pq0[b]; }
        float m = s * (1.f / B_);
        float var = q * (1.f / B_) - m * m;
        float inv = rsqrtf(var + EPS);
        float sc = vg3[0] * inv;
        bc[0] = sc;
        bc[1] = vbe3[0] - m * sc;
    }
    __syncthreads();
    if (tid < 64) vs[tid] = fmaxf(fmaf(yv[tid], bc[0], bc[1]), 0.f);
    __syncthreads();
}

// ---------------- the persistent mega-kernel ----------------
__global__ void __launch_bounds__(THREADS, 1) mega(
    const float* __restrict__ x, const float* __restrict__ xi,
    const float* __restrict__ tg, const float* __restrict__ W1,
    const float* __restrict__ b1, const float* __restrict__ g1,
    const float* __restrict__ be1, const float* __restrict__ W2,
    const float* __restrict__ b2, const float* __restrict__ g2,
    const float* __restrict__ be2, const float* __restrict__ W3,
    const float* __restrict__ b3, const float* __restrict__ vW1,
    const float* __restrict__ vb1, const float* __restrict__ vg1,
    const float* __restrict__ vbe1, const float* __restrict__ vW2,
    const float* __restrict__ vb2, const float* __restrict__ vg2,
    const float* __restrict__ vbe2, const float* __restrict__ vW3,
    const float* __restrict__ vb3, const float* __restrict__ vg3,
    const float* __restrict__ vbe3, float* __restrict__ out) {
    extern __shared__ char smc[];
    const int bid = blockIdx.x, tid = threadIdx.x;

    // ---- phase 0: convert weights + x to fp16; zero atomic slots + Y pad cols ----
    {
        const int gt = bid * THREADS + tid, gs = NBLK * THREADS;
        for (int i = gt; i < T_ * H_ * D_; i += gs)
            g_w[GW1 + i] = __float2half(W1[i]);
        for (int i = gt; i < T_ * H_ * HP; i += gs) {
            int r = i / HP, k = i - r * HP;
            g_w[GW2 + i] = (k < H_) ? __float2half(W2[r * H_ + k]) : __float2half(0.f);
        }
        for (int i = gt; i < T_ * D_ * HP; i += gs) {
            int r = i / HP, k = i - r * HP;
            g_w[GW3 + i] = (k < H_) ? __float2half(W3[r * H_ + k]) : __float2half(0.f);
        }
        for (int i = gt; i < H_ * D_; i += gs)
            g_w[GVW1 + i] = __float2half(vW1[i]);
        for (int i = gt; i < H_ * HP; i += gs) {
            int r = i / HP, k = i - r * HP;
            g_w[GVW2 + i] = (k < H_) ? __float2half(vW2[r * H_ + k]) : __float2half(0.f);
        }
        for (int i = gt; i < B_ * D_; i += gs) g_xh[i] = __float2half(x[i]);
        for (int i = gt; i < 3 * 288; i += gs) {
            g_as[i] = 0.f;
            g_aq[i] = 0.f;
        }
        // pad columns [266,272) of h1/h2 are zero forever (epi_stats never writes them)
        for (int i = gt; i < B_ * 6; i += gs) {
            int r = i / 6, k = H_ + (i - r * 6);
            g_h1[(size_t)r * HP + k] = __float2half(0.f);
            g_h2[(size_t)r * HP + k] = __float2half(0.f);
        }
    }
    gbar();

    int bn = 0;  // vector-BN counter (slot = bn % 3)

    // ---- v0 network ----
    issue2(g_xh, g_w + GVW1, 256, 266, smc, bid, tid);
    {
        float acc[2][5][4] = {};
        do_gemm<4, false>(g_xh, g_w + GVW1, 256, 266, 288, 0, 0, nullptr, nullptr, smc,
                          bid, tid, acc);
        epi_stats(acc, vb1, g_h1, 266, bn % 3, smc, bid, tid);
    }
    issue2(g_h1, g_w + GVW2, 272, 266, smc, bid, tid);
    gbar();
    {
        float acc[2][5][4] = {};
        do_gemm<5, true>(g_h1, g_w + GVW2, 272, 266, 288, bn % 3, (bn + 2) % 3, vg1,
                         vbe1, smc, bid, tid, acc);
        bn++;
        epi_stats(acc, vb2, g_h2, 266, bn % 3, smc, bid, tid);
    }
    gbar();
    finalize_direct(bn % 3, (bn + 2) % 3, vg2, vbe2, smc, tid);
    bn++;
    v3_part(g_h2, vW3, vb3, smc, bid, tid);
    gbar();
    v0_final(vg3, vbe3, smc, tid);

    issue2(g_xh, g_w + GW1, 256, 266, smc, bid, tid);

    // ---- time-stepping scan ----
    for (int t = 0; t < T_; t++) {
        const float* xsrc = (t == 0) ? x : g_x;
        const hf* W1t = g_w + GW1 + (size_t)t * H_ * D_;
        const hf* W2t = g_w + GW2 + (size_t)t * H_ * HP;
        const hf* W3t = g_w + GW3 + (size_t)t * D_ * HP;
        const float* b1t = b1 + (size_t)t * H_;
        const float* g1t = g1 + (size_t)t * H_;
        const float* be1t = be1 + (size_t)t * H_;
        const float* b2t = b2 + (size_t)t * H_;
        const float* g2t = g2 + (size_t)t * H_;
        const float* be2t = be2 + (size_t)t * H_;
        const float* b3t = b3 + (size_t)t * D_;
        const float* xit = xi + (size_t)t * B_ * D_;

        {
            float acc[2][5][4] = {};
            do_gemm<4, false>(g_xh, W1t, 256, 266, 288, 0, 0, nullptr, nullptr, smc,
                              bid, tid, acc);
            epi_stats(acc, b1t, g_h1, 266, bn % 3, smc, bid, tid);
        }
        issue2(g_h1, W2t, 272, 266, smc, bid, tid);
        gbar();
        {
            float acc[2][5][4] = {};
            do_gemm<5, true>(g_h1, W2t, 272, 266, 288, bn % 3, (bn + 2) % 3, g1t, be1t,
                             smc, bid, tid, acc);
            bn++;
            epi_stats(acc, b2t, g_h2, 266, bn % 3, smc, bid, tid);
        }
        issue2(g_h2, W3t, 272, 256, smc, bid, tid);
        gbar();
        {
            float acc[2][5][4] = {};
            do_gemm<5, true>(g_h2, W3t, 272, 256, 256, bn % 3, (bn + 2) % 3, g2t, be2t,
                             smc, bid, tid, acc);
            bn++;
            float ht = tg[t + 1] - tg[t];
            float* xdst = (t == T_ - 1) ? (out + B_) : g_x;
            hf* xh = (t == T_ - 1) ? nullptr : g_xh;
            epi_update(acc, b3t, xit, xsrc, xdst, xh, ht, smc, bid, tid);
        }
        if (t + 1 < T_) {
            issue2(g_xh, g_w + GW1 + (size_t)(t + 1) * H_ * D_, 256, 266, smc, bid, tid);
        }
    }

    // ---- output v ----
    if (tid < 64) out[bid * 64 + tid] = ((float*)(smc + OFF_VS))[tid];
}

// ---------------- host ----------------
extern "C" void kernel_launch(void* const* d_in, const int* in_sizes, int n_in,
                              void* d_out, int out_size) {
    const float* x    = (const float*)d_in[0];
    const float* xi   = (const float*)d_in[1];
    const float* tg   = (const float*)d_in[2];
    const float* W1   = (const float*)d_in[3];
    const float* b1   = (const float*)d_in[4];
    const float* g1   = (const float*)d_in[5];
    const float* be1  = (const float*)d_in[6];
    const float* W2   = (const float*)d_in[7];
    const float* b2   = (const float*)d_in[8];
    const float* g2   = (const float*)d_in[9];
    const float* be2  = (const float*)d_in[10];
    const float* W3   = (const float*)d_in[11];
    const float* b3   = (const float*)d_in[12];
    const float* vW1  = (const float*)d_in[13];
    const float* vb1  = (const float*)d_in[14];
    const float* vg1  = (const float*)d_in[15];
    const float* vbe1 = (const float*)d_in[16];
    const float* vW2  = (const float*)d_in[17];
    const float* vb2  = (const float*)d_in[18];
    const float* vg2  = (const float*)d_in[19];
    const float* vbe2 = (const float*)d_in[20];
    const float* vW3  = (const float*)d_in[21];
    const float* vb3  = (const float*)d_in[22];
    const float* vg3  = (const float*)d_in[23];
    const float* vbe3 = (const float*)d_in[24];

    cudaFuncSetAttribute(mega, cudaFuncAttributeMaxDynamicSharedMemorySize, SMEM_BYTES);
    mega<<<NBLK, THREADS, SMEM_BYTES>>>(x, xi, tg, W1, b1, g1, be1, W2, b2, g2, be2,
                                        W3, b3, vW1, vb1, vg1, vbe1, vW2, vb2, vg2,
                                        vbe2, vW3, vb3, vg3, vbe3, (float*)d_out);
}